// round 5
// baseline (speedup 1.0000x reference)
#include <cuda_runtime.h>
#include <stdint.h>

#define NN 1024
#define EE 32
#define JH 512   // columns per j-half

// Scratch (no allocations allowed)
__device__ float g_rows[256][32][4];   // per-CTA per-row partial {T,A,P,C}
__device__ unsigned int g_pair[128];   // per (b,itile) arrival counters
__device__ float g_part[128];          // per-pair loss partials
__device__ unsigned int g_done = 0;    // global finisher counter

// ---------------------------------------------------------------------------
// One launch. grid (64 = itile*2+half, 4 batches) x 256 threads, 2 CTAs/SM.
// CTA computes rows [i0,i0+32) x cols [j0,j0+512): Gram via smem register tile,
// fused branchless epilogue, additive row sums {T,A,P,C}. Second CTA of each
// (b,itile) pair merges halves + closed form; last finisher reduces 128 parts.
// ---------------------------------------------------------------------------
__global__ void __launch_bounds__(256, 2)
fused_kernel(const float* __restrict__ emb,
             const float* __restrict__ coords,
             const int*   __restrict__ mask,
             float*       __restrict__ out) {
    extern __shared__ char smem[];
    float* sYJ = reinterpret_cast<float*>(smem);    // [32][512] e-major, 64KB
    float* sNJ = sYJ + EE * JH;                     // [512]
    float* sYI = sNJ + JH;                          // [32][32]  e-major, 4KB
    float* sNI = sYI + EE * 32;                     // [32]
    __shared__ int sRole, sLast;

    const int tid   = threadIdx.x;
    const int warp  = tid >> 5;
    const int lane  = tid & 31;
    const int itile = blockIdx.x >> 1;
    const int half  = blockIdx.x & 1;
    const int b     = blockIdx.y;
    const int i0    = itile * 32;
    const int j0    = half * JH;
    const int cta   = (b * 32 + itile) * 2 + half;
    const int pair  = b * 32 + itile;

    // ---------------- Phase A: build smem tiles -----------------------------
#pragma unroll
    for (int k = 0; k < 2; k++) {
        const int jr = tid + k * 256;               // 0..511 local col
        const int gj = j0 + jr;
        const float* ep = emb + ((size_t)(b * NN + gj)) * EE;
        float v[EE];
#pragma unroll
        for (int e = 0; e < EE; e += 4) {
            float4 t = *reinterpret_cast<const float4*>(ep + e);
            v[e] = t.x; v[e + 1] = t.y; v[e + 2] = t.z; v[e + 3] = t.w;
        }
        float2 c2 = *reinterpret_cast<const float2*>(coords + ((size_t)(b * NN + gj)) * 2);
        v[0] += c2.x; v[1] += c2.y;
        float n = 0.f;
#pragma unroll
        for (int e = 0; e < EE; e++) {
            sYJ[e * JH + jr] = v[e];                // lanes consecutive: no conflict
            n += v[e] * v[e];
        }
        sNJ[jr] = n;
    }
    if (tid < 32) {
        const int gi = i0 + tid;
        const float* ep = emb + ((size_t)(b * NN + gi)) * EE;
        float v[EE];
#pragma unroll
        for (int e = 0; e < EE; e += 4) {
            float4 t = *reinterpret_cast<const float4*>(ep + e);
            v[e] = t.x; v[e + 1] = t.y; v[e + 2] = t.z; v[e + 3] = t.w;
        }
        float2 c2 = *reinterpret_cast<const float2*>(coords + ((size_t)(b * NN + gi)) * 2);
        v[0] += c2.x; v[1] += c2.y;
        float n = 0.f;
#pragma unroll
        for (int e = 0; e < EE; e++) {
            sYI[e * 32 + tid] = v[e];
            n += v[e] * v[e];
        }
        sNI[tid] = n;
    }
    __syncthreads();

    // ---------------- Phase B: Gram + fused epilogue ------------------------
    const float4* sYJ4 = reinterpret_cast<const float4*>(sYJ);
    const float4* sYI4 = reinterpret_cast<const float4*>(sYI);
    const float4* sNJ4 = reinterpret_cast<const float4*>(sNJ);

    const int* mrow[4];
#pragma unroll
    for (int r = 0; r < 4; r++)
        mrow[r] = mask + ((size_t)b * NN + (size_t)(i0 + warp * 4 + r)) * NN + j0;

    float Tr[4] = {0, 0, 0, 0}, Ar[4] = {0, 0, 0, 0};
    float Pr[4] = {0, 0, 0, 0}, Cr[4] = {0, 0, 0, 0};
    float nis[4];
#pragma unroll
    for (int r = 0; r < 4; r++) nis[r] = sNI[warp * 4 + r];

    for (int jc = 0; jc < 4; ++jc) {                // 4 x 128 columns
        float acc[4][4];
#pragma unroll
        for (int r = 0; r < 4; r++)
#pragma unroll
            for (int c = 0; c < 4; c++) acc[r][c] = 0.f;

#pragma unroll
        for (int e = 0; e < EE; e++) {
            float4 a  = sYI4[e * 8 + warp];             // broadcast (rows warp*4..+3)
            float4 bb = sYJ4[e * (JH / 4) + jc * 32 + lane];  // lane-consecutive
            acc[0][0] += a.x * bb.x; acc[0][1] += a.x * bb.y; acc[0][2] += a.x * bb.z; acc[0][3] += a.x * bb.w;
            acc[1][0] += a.y * bb.x; acc[1][1] += a.y * bb.y; acc[1][2] += a.y * bb.z; acc[1][3] += a.y * bb.w;
            acc[2][0] += a.z * bb.x; acc[2][1] += a.z * bb.y; acc[2][2] += a.z * bb.z; acc[2][3] += a.z * bb.w;
            acc[3][0] += a.w * bb.x; acc[3][1] += a.w * bb.y; acc[3][2] += a.w * bb.z; acc[3][3] += a.w * bb.w;
        }

        const int jb = jc * 128 + lane * 4;
        float4 njv = sNJ4[jb >> 2];
        float nj[4] = {njv.x, njv.y, njv.z, njv.w};

#pragma unroll
        for (int r = 0; r < 4; r++) {
            const float ni = nis[r];
            int4 m4 = *reinterpret_cast<const int4*>(mrow[r] + jb);
            float mf[4] = {(float)m4.x, (float)m4.y, (float)m4.z, (float)m4.w};
#pragma unroll
            for (int c = 0; c < 4; c++) {
                float ssq  = fmaxf(fmaf(-2.f, acc[r][c], ni + nj[c]), 0.f);
                float dist = ssq * rsqrtf(fmaxf(ssq, 1e-37f));   // MUFU only; 0 -> 0
                float u    = __expf(dist - 5.f);
                float sim  = __fdividef(1.f, 1.f + u);           // sigmoid(5-dist)
                float ex   = __expf(sim);
                float m    = mf[c];
                Tr[r] += ex;
                Ar[r]  = fmaf(m, ex, Ar[r]);
                Pr[r]  = fmaf(m, sim, Pr[r]);
                Cr[r] += m;
            }
        }
    }

    // Warp-reduce row sums; lane0 publishes to global scratch
#pragma unroll
    for (int r = 0; r < 4; r++) {
        float t = Tr[r], a = Ar[r], p = Pr[r], cn = Cr[r];
#pragma unroll
        for (int o = 16; o > 0; o >>= 1) {
            t  += __shfl_down_sync(0xffffffffu, t,  o);
            a  += __shfl_down_sync(0xffffffffu, a,  o);
            p  += __shfl_down_sync(0xffffffffu, p,  o);
            cn += __shfl_down_sync(0xffffffffu, cn, o);
        }
        if (lane == 0) {
            float* gp = g_rows[cta][warp * 4 + r];
            gp[0] = t; gp[1] = a; gp[2] = p; gp[3] = cn;
        }
    }
    __threadfence();
    __syncthreads();
    if (tid == 0) sRole = (atomicAdd(&g_pair[pair], 1u) == 1u);
    __syncthreads();

    if (sRole) {                                    // pair finisher
        __threadfence();
        const float EXDIAG = 2.70009072f;           // e^{sigmoid(5)}
        if (tid < 32) {
            const int row = tid;
            const int i   = i0 + row;
            const float* h0 = g_rows[pair * 2 + 0][row];
            const float* h1 = g_rows[pair * 2 + 1][row];
            float T = h0[0] + h1[0];
            float A = h0[1] + h1[1];
            float P = h0[2] + h1[2];
            float C = h0[3] + h1[3];
            float md = (mask[((size_t)b * NN + i) * NN + i] != 0) ? 1.f : 0.f;
            float S  = T - A - (1.f - md) * EXDIAG;
            float L  = __logf(S);
            float contrib = C * L - P + A * __fdividef(1.f, S);  // 1st-order log1p
#pragma unroll
            for (int o = 16; o > 0; o >>= 1)
                contrib += __shfl_down_sync(0xffffffffu, contrib, o);
            if (tid == 0) {
                g_part[pair]  = contrib;
                g_pair[pair]  = 0;                  // reset for next replay
            }
        }
        __threadfence();
        __syncthreads();
        if (tid == 0) sLast = (atomicAdd(&g_done, 1u) == 127u);
        __syncthreads();

        if (sLast) {                                // deterministic final tree
            __threadfence();
            double* dsh = reinterpret_cast<double*>(sYJ);
            if (tid < 128) dsh[tid] = (double)g_part[tid];
            __syncthreads();
#pragma unroll
            for (int s = 64; s > 0; s >>= 1) {
                if (tid < s) dsh[tid] += dsh[tid + s];
                __syncthreads();
            }
            if (tid == 0) {
                out[0] = (float)dsh[0];
                g_done = 0;                         // reset for next replay
            }
        }
    }
}

// ---------------------------------------------------------------------------
extern "C" void kernel_launch(void* const* d_in, const int* in_sizes, int n_in,
                              void* d_out, int out_size) {
    (void)in_sizes; (void)n_in; (void)out_size;
    const float* emb    = (const float*)d_in[0];   // [4,1024,32]
    const float* coords = (const float*)d_in[1];   // [4,1024,2]
    const int*   mask   = (const int*)d_in[2];     // [4,1024,1024] bool->int32
    float* out          = (float*)d_out;           // scalar

    size_t smem = (size_t)EE * JH * sizeof(float)   // sYJ   65536
                + (size_t)JH * sizeof(float)        // sNJ    2048
                + (size_t)EE * 32 * sizeof(float)   // sYI    4096
                + 32 * sizeof(float);               // sNI     128
    cudaFuncSetAttribute(fused_kernel, cudaFuncAttributeMaxDynamicSharedMemorySize,
                         (int)smem);
    fused_kernel<<<dim3(64, 4), 256, smem>>>(emb, coords, mask, out);
}

// round 8
// speedup vs baseline: 1.3686x; 1.3686x over previous
#include <cuda_runtime.h>
#include <stdint.h>

#define NN 1024
#define EE 32

// Scratch (no allocations allowed)
__device__ float g_part[128];
__device__ unsigned int g_done = 0;

// Packed f32x2 helpers (Blackwell)
#define PACK2(d, s) \
    asm("mov.b64 %0, {%1, %1};" : "=l"(d) : "r"(__float_as_uint(s)))
#define FFMA2(d, a, b) \
    asm("fma.rn.f32x2 %0, %1, %2, %3;" : "=l"(d) : "l"(a), "l"(b), "l"(d))
#define UNPK2(lo, hi, s) \
    asm("mov.b64 {%0, %1}, %2;" : "=r"(lo), "=r"(hi) : "l"(s))

// ---------------------------------------------------------------------------
// One launch. grid (32 i-tiles, 4 batches) x 256 threads, 1 CTA/SM (135KB smem).
// Per CTA: rows [i0,i0+32) x all 1024 j. Gram via f32x2 packed FMA on smem
// register tiles; mask LDGs software-pipelined one jc ahead; branchless
// epilogue accumulating additive row sums {T, A, P, C}; analytic diag fix.
// ---------------------------------------------------------------------------
__global__ void __launch_bounds__(256, 1)
fused_kernel(const float* __restrict__ emb,
             const float* __restrict__ coords,
             const int*   __restrict__ mask,
             float*       __restrict__ out) {
    extern __shared__ char smem[];
    float* sYT  = reinterpret_cast<float*>(smem);   // [32][1024] e-major
    float* sN   = sYT + EE * NN;                    // [1024]
    float* sRed = sN + NN;                          // [8]
    __shared__ int sIsLast;

    const int tid  = threadIdx.x;
    const int b    = blockIdx.y;
    const int i0   = blockIdx.x * 32;
    const int warp = tid >> 5;
    const int lane = tid & 31;

    // ---------------- Phase A: build yT + norms (4 rows/thread) -------------
#pragma unroll
    for (int k = 0; k < 4; k++) {
        const int j = tid + k * 256;
        const float* ep = emb + ((size_t)(b * NN + j)) * EE;
        float v[EE];
#pragma unroll
        for (int e = 0; e < EE; e += 4) {
            float4 t = *reinterpret_cast<const float4*>(ep + e);
            v[e] = t.x; v[e + 1] = t.y; v[e + 2] = t.z; v[e + 3] = t.w;
        }
        float2 c2 = *reinterpret_cast<const float2*>(coords + ((size_t)(b * NN + j)) * 2);
        v[0] += c2.x; v[1] += c2.y;
        float n = 0.f;
#pragma unroll
        for (int e = 0; e < EE; e++) {
            sYT[e * NN + j] = v[e];
            n += v[e] * v[e];
        }
        sN[j] = n;
    }
    __syncthreads();

    // ---------------- Phase B: f32x2 Gram + pipelined mask + epilogue -------
    const ulonglong2* sYT2 = reinterpret_cast<const ulonglong2*>(sYT);  // 16B pairs
    const float4*     sYI4 = reinterpret_cast<const float4*>(sYT);
    const float4*     sN4  = reinterpret_cast<const float4*>(sN);

    const int* mrow[4];
#pragma unroll
    for (int r = 0; r < 4; r++)
        mrow[r] = mask + ((size_t)b * NN + (size_t)(i0 + warp * 4 + r)) * NN;

    float Tr[4] = {0, 0, 0, 0}, Ar[4] = {0, 0, 0, 0}, Pr[4] = {0, 0, 0, 0};
    int   Ci[4] = {0, 0, 0, 0};
    float nis[4];
#pragma unroll
    for (int r = 0; r < 4; r++) nis[r] = sN[i0 + warp * 4 + r];

    // prefetch mask for jc = 0
    int4 mbuf[4];
    {
        const int jb0 = lane * 4;
#pragma unroll
        for (int r = 0; r < 4; r++)
            mbuf[r] = *reinterpret_cast<const int4*>(mrow[r] + jb0);
    }

#pragma unroll 1
    for (int jc = 0; jc < 8; ++jc) {
        // prefetch next iteration's mask (clamped; hidden under the Gram)
        int4 mnext[4];
        {
            const int jcn = (jc < 7) ? jc + 1 : 7;
            const int jbn = jcn * 128 + lane * 4;
#pragma unroll
            for (int r = 0; r < 4; r++)
                mnext[r] = *reinterpret_cast<const int4*>(mrow[r] + jbn);
        }

        // Gram: acc pairs [row][pair] over 4 rows x 4 cols (2 f32x2 pairs)
        unsigned long long acc[4][2] = {{0, 0}, {0, 0}, {0, 0}, {0, 0}};
#pragma unroll
        for (int e = 0; e < EE; e++) {
            float4     a  = sYI4[e * (NN / 4) + (i0 >> 2) + warp];  // broadcast
            ulonglong2 bv = sYT2[e * (NN / 4) + jc * 32 + lane];    // lane-consec
            unsigned long long a0, a1, a2, a3;
            PACK2(a0, a.x); PACK2(a1, a.y); PACK2(a2, a.z); PACK2(a3, a.w);
            FFMA2(acc[0][0], a0, bv.x); FFMA2(acc[0][1], a0, bv.y);
            FFMA2(acc[1][0], a1, bv.x); FFMA2(acc[1][1], a1, bv.y);
            FFMA2(acc[2][0], a2, bv.x); FFMA2(acc[2][1], a2, bv.y);
            FFMA2(acc[3][0], a3, bv.x); FFMA2(acc[3][1], a3, bv.y);
        }

        const int jb = jc * 128 + lane * 4;
        float4 njv = sN4[jb >> 2];
        float nj[4] = {njv.x, njv.y, njv.z, njv.w};
        const float L2E = 1.44269504f;        // log2(e)

#pragma unroll
        for (int r = 0; r < 4; r++) {
            const float ni = nis[r];
            float av[4];
            {
                unsigned u0, u1, u2, u3;
                UNPK2(u0, u1, acc[r][0]); UNPK2(u2, u3, acc[r][1]);
                av[0] = __uint_as_float(u0); av[1] = __uint_as_float(u1);
                av[2] = __uint_as_float(u2); av[3] = __uint_as_float(u3);
            }
            int4 m4 = mbuf[r];
            int  mi[4] = {m4.x, m4.y, m4.z, m4.w};
#pragma unroll
            for (int c = 0; c < 4; c++) {
                float ssq  = fmaxf(fmaf(-2.f, av[c], ni + nj[c]), 0.f);
                float dist = ssq * rsqrtf(fmaxf(ssq, 1e-37f));      // MUFU only
                float u    = exp2f(fmaf(dist, L2E, -5.f * L2E));    // e^(dist-5)
                float sim  = __fdividef(1.f, 1.f + u);              // sigmoid(5-dist)
                float ex   = exp2f(sim * L2E);                      // e^sim
                float m    = (float)mi[c];
                Tr[r] += ex;
                Ar[r]  = fmaf(m, ex, Ar[r]);
                Pr[r]  = fmaf(m, sim, Pr[r]);
                Ci[r] += mi[c];
            }
            mbuf[r] = mnext[r];
        }
    }

    // diag mask for this warp's 4 rows (lanes 0..3)
    int mdiag_l = 0;
    if (lane < 4) {
        const int i = i0 + warp * 4 + lane;
        mdiag_l = mask[((size_t)b * NN + i) * NN + i];
    }

    // ---------------- Phase C: closed form + reductions ---------------------
    const float EXDIAG = 2.70009072f;   // e^{sigmoid(5)}
    float csum = 0.f;
#pragma unroll
    for (int r = 0; r < 4; r++) {
        float t = Tr[r], a = Ar[r], p = Pr[r], cn = (float)Ci[r];
#pragma unroll
        for (int o = 16; o > 0; o >>= 1) {
            t  += __shfl_down_sync(0xffffffffu, t,  o);
            a  += __shfl_down_sync(0xffffffffu, a,  o);
            p  += __shfl_down_sync(0xffffffffu, p,  o);
            cn += __shfl_down_sync(0xffffffffu, cn, o);
        }
        float md = (float)__shfl_sync(0xffffffffu, mdiag_l, r);
        if (lane == 0) {
            float S = t - a - (1.f - md) * EXDIAG;   // negatives' exp-sum
            float L = __logf(S);
            csum += cn * L - p + a * __fdividef(1.f, S);   // 1st-order log1p
        }
    }
    if (lane == 0) sRed[warp] = csum;
    __syncthreads();

    if (tid == 0) {
        float tsum = 0.f;
#pragma unroll
        for (int w = 0; w < 8; w++) tsum += sRed[w];
        g_part[b * 32 + blockIdx.x] = tsum;
        __threadfence();
        unsigned v = atomicAdd(&g_done, 1u);
        sIsLast = (v == 127u);
    }
    __syncthreads();

    // Last CTA: deterministic fixed-order tree over the 128 partials
    if (sIsLast) {
        double* dsh = reinterpret_cast<double*>(sYT);
        if (tid < 128) dsh[tid] = (double)g_part[tid];
        __syncthreads();
#pragma unroll
        for (int s = 64; s > 0; s >>= 1) {
            if (tid < s) dsh[tid] += dsh[tid + s];
            __syncthreads();
        }
        if (tid == 0) {
            out[0] = (float)dsh[0];
            g_done = 0;                 // reset for next replay
        }
    }
}

// ---------------------------------------------------------------------------
extern "C" void kernel_launch(void* const* d_in, const int* in_sizes, int n_in,
                              void* d_out, int out_size) {
    (void)in_sizes; (void)n_in; (void)out_size;
    const float* emb    = (const float*)d_in[0];   // [4,1024,32]
    const float* coords = (const float*)d_in[1];   // [4,1024,2]
    const int*   mask   = (const int*)d_in[2];     // [4,1024,1024] bool->int32
    float* out          = (float*)d_out;           // scalar

    size_t smem = (size_t)EE * NN * sizeof(float)   // yT    131072
                + (size_t)NN * sizeof(float)        // norms   4096
                + 64;                               // reduction slots
    cudaFuncSetAttribute(fused_kernel, cudaFuncAttributeMaxDynamicSharedMemorySize,
                         (int)smem);
    fused_kernel<<<dim3(32, 4), 256, smem>>>(emb, coords, mask, out);
}